// round 11
// baseline (speedup 1.0000x reference)
#include <cuda_runtime.h>
#include <cuda_bf16.h>
#include <cstdint>

using ull = unsigned long long;

__device__ __forceinline__ ull pk(float lo, float hi) {
  ull r; asm("mov.b64 %0, {%1,%2};" : "=l"(r) : "f"(lo), "f"(hi)); return r;
}
__device__ __forceinline__ void upk(ull v, float& lo, float& hi) {
  asm("mov.b64 {%0,%1}, %2;" : "=f"(lo), "=f"(hi) : "l"(v));
}
__device__ __forceinline__ ull ffma2(ull a, ull b, ull c) {
  ull d; asm("fma.rn.f32x2 %0, %1, %2, %3;" : "=l"(d) : "l"(a), "l"(b), "l"(c)); return d;
}
__device__ __forceinline__ void cpa16(uint32_t dst, const void* src) {
  asm volatile("cp.async.ca.shared.global [%0], [%1], 16;" :: "r"(dst), "l"(src));
}
#define CP_COMMIT() asm volatile("cp.async.commit_group;")
#define CP_WAIT1()  asm volatile("cp.async.wait_group 1;")

// Scalar complex MAC: (sr,si) += (ar,ai)*(br,bi)
#define CMAC(sr, si, ar, ai, br, bi) do { \
  (sr) = fmaf((ar), (br), (sr)); (sr) = fmaf(-(ai), (bi), (sr)); \
  (si) = fmaf((ar), (bi), (si)); (si) = fmaf((ai), (br), (si)); } while (0)

constexpr int Lc = 2048;
constexpr int T = 16;                   // steps per chunk
constexpr int NCHUNK = Lc / T;          // 128
constexpr int NSEQ = 256;               // B*C
constexpr int NUNIT = NSEQ * NCHUNK;    // 32768

__device__ float2 g_M2[NUNIT * 64];     // 16 MB: chunk transition matrices
__device__ float2 g_v2[NUNIT * 8];      // 2 MB: chunk offsets
__device__ float2 g_E2[NUNIT * 8];      // 2 MB: entering states

constexpr int FU_STRIDE = 1232;

// ---------------------------------------------------------------------------
// Kernel 1: fold T steps into (M, v). 64 threads = 8 units; 8 lanes/unit;
// lane h owns M column h and v row h (halved register state vs R9 for
// occupancy; no forced reg cap).
// ---------------------------------------------------------------------------
__global__ __launch_bounds__(64, 8) void k_fold(
    const float* __restrict__ Are, const float* __restrict__ Aim,
    const float* __restrict__ Xre, const float* __restrict__ Xim)
{
  __shared__ __align__(16) char smraw[8 * FU_STRIDE];

  const int tid = threadIdx.x;
  const int u = tid >> 3, h = tid & 7;
  const int bid = blockIdx.x;                 // = ((b*128 + chunk)*8 + cg)
  const int cg = bid & 7;
  const int chunk = (bid >> 3) & 127;
  const int b = bid >> 10;
  const int c = cg * 8 + u;
  const int unit = (b * 64 + c) * NCHUNK + chunk;
  const int t0 = chunk * T;

  const float* aRe = Are + ((size_t)(b * Lc + t0) * 64 + c) * 64;
  const float* aIm = Aim + ((size_t)(b * Lc + t0) * 64 + c) * 64;
  const float* xRe = Xre + ((size_t)(b * Lc + t0) * 64 + c) * 8;
  const float* xIm = Xim + ((size_t)(b * Lc + t0) * 64 + c) * 8;

  char* su = smraw + u * FU_STRIDE;
  const uint32_t suA = (uint32_t)__cvta_generic_to_shared(su);
  ull* vbuf = (ull*)(su + 1152);

  // Lane h stages A row h (re 32 B + im 32 B); lanes 0/1 stage x re/im.
  #define STAGE(t, st) do { \
    const float* r_ = aRe + (t) * 4096 + h * 8; \
    const float* i_ = aIm + (t) * 4096 + h * 8; \
    uint32_t d_ = suA + (st) * 512 + h * 32; \
    cpa16(d_, r_); cpa16(d_ + 16, r_ + 4); \
    cpa16(d_ + 256, i_); cpa16(d_ + 272, i_ + 4); \
    if (h == 0) { const float* x_ = xRe + (t) * 512; uint32_t dx_ = suA + 1024 + (st) * 64; \
      cpa16(dx_, x_); cpa16(dx_ + 16, x_ + 4); } \
    if (h == 1) { const float* x_ = xIm + (t) * 512; uint32_t dx_ = suA + 1024 + (st) * 64 + 32; \
      cpa16(dx_, x_); cpa16(dx_ + 16, x_ + 4); } \
  } while (0)

  STAGE(0, 0); CP_COMMIT();
  STAGE(1, 1); CP_COMMIT();
  CP_WAIT1();
  __syncwarp();

  // Init M = A(t0): column h, packed (re,im); v = X(t0).
  ull Mc[8];
  {
    const float* sre = (const float*)(su);
    const float* sim = (const float*)(su + 256);
    #pragma unroll
    for (int i = 0; i < 8; i++)
      Mc[i] = pk(sre[i * 8 + h], sim[i * 8 + h]);
    const float* xr = (const float*)(su + 1024);
    const float* xi = xr + 8;
    vbuf[h] = pk(xr[h], xi[h]);
  }
  __syncwarp();

  ull vnew = vbuf[h];

  for (int s = 1; s < T; ++s) {
    if (s + 1 < T) STAGE(s + 1, (s + 1) & 1);
    CP_COMMIT();
    CP_WAIT1();
    __syncwarp();

    const char* stg = su + (s & 1) * 512;
    const float* sre = (const float*)(stg);
    const float* sim = (const float*)(stg + 256);

    // M <- A(t_s) @ M : column h.
    ull n[8];
    #pragma unroll
    for (int i = 0; i < 8; i++) {
      const float4* rr = (const float4*)(sre + i * 8);
      const float4* ii = (const float4*)(sim + i * 8);
      float4 ra = rr[0], rb = rr[1], ia = ii[0], ib = ii[1];
      ull a1 = 0, a2 = 0;
      #define STEPK(RF, IF, K) do { \
        ull dr_ = pk((RF), (RF)); ull di_ = pk((IF), (IF)); \
        a1 = ffma2(dr_, Mc[K], a1); a2 = ffma2(di_, Mc[K], a2); } while (0)
      STEPK(ra.x, ia.x, 0); STEPK(ra.y, ia.y, 1);
      STEPK(ra.z, ia.z, 2); STEPK(ra.w, ia.w, 3);
      STEPK(rb.x, ib.x, 4); STEPK(rb.y, ib.y, 5);
      STEPK(rb.z, ib.z, 6); STEPK(rb.w, ib.w, 7);
      #undef STEPK
      float l1, h1, l2, h2;
      upk(a1, l1, h1); upk(a2, l2, h2);
      n[i] = pk(l1 - h2, h1 + l2);
    }

    // v <- A(t_s) v + x(t_s): row h.
    {
      const ulonglong2* vb2 = (const ulonglong2*)vbuf;
      ulonglong2 q0 = vb2[0], q1 = vb2[1], q2 = vb2[2], q3 = vb2[3];
      ull vv[8] = {q0.x, q0.y, q1.x, q1.y, q2.x, q2.y, q3.x, q3.y};
      const float* xr = (const float*)(su + 1024 + (s & 1) * 64);
      const float* xi = xr + 8;
      const float4* rr = (const float4*)(sre + h * 8);
      const float4* ii = (const float4*)(sim + h * 8);
      float4 ra = rr[0], rb = rr[1], ia = ii[0], ib = ii[1];
      ull a1 = pk(xr[h], xi[h]), a2 = 0;
      #define VK(RF, IF, K) do { \
        ull dr_ = pk((RF), (RF)); ull di_ = pk((IF), (IF)); \
        a1 = ffma2(dr_, vv[K], a1); a2 = ffma2(di_, vv[K], a2); } while (0)
      VK(ra.x, ia.x, 0); VK(ra.y, ia.y, 1); VK(ra.z, ia.z, 2); VK(ra.w, ia.w, 3);
      VK(rb.x, ib.x, 4); VK(rb.y, ib.y, 5); VK(rb.z, ib.z, 6); VK(rb.w, ib.w, 7);
      #undef VK
      float l1, h1, l2, h2; upk(a1, l1, h1); upk(a2, l2, h2);
      vnew = pk(l1 - h2, h1 + l2);
    }

    #pragma unroll
    for (int i = 0; i < 8; i++) Mc[i] = n[i];
    __syncwarp();               // all lanes done reading v-old and this stage
    vbuf[h] = vnew;
  }

  // Store column h of M (row-major for k_scan's row reads) and v[h].
  float2* gm = g_M2 + (size_t)unit * 64;
  #pragma unroll
  for (int i = 0; i < 8; i++) {
    float re, im; upk(Mc[i], re, im);
    gm[i * 8 + h] = make_float2(re, im);
  }
  {
    float re, im; upk(vnew, re, im);
    g_v2[unit * 8 + h] = make_float2(re, im);
  }
  #undef STAGE
}

// ---------------------------------------------------------------------------
// Kernel 2: serial scan over NCHUNK chunk summaries per sequence.
// 4-deep register prefetch ring; 64 CTAs x 32 threads (4 seqs per CTA).
// ---------------------------------------------------------------------------
__global__ void k_scan()
{
  const int gid = blockIdx.x * blockDim.x + threadIdx.x;
  const int seq = gid >> 3, i = gid & 7;
  if (seq >= NSEQ) return;
  float er = 0.f, ei = 0.f;             // state entering chunk 0 is zero

  const float2* mbase = g_M2 + (size_t)(seq * NCHUNK) * 64;
  const float2* vbase = g_v2 + (size_t)(seq * NCHUNK) * 8;
  float2* ebase = g_E2 + (size_t)(seq * NCHUNK) * 8;

  float4 m[4][4];
  float2 vv[4];
  #pragma unroll
  for (int p = 0; p < 4; p++) {
    const float4* mp = (const float4*)(mbase + p * 64 + i * 8);
    m[p][0] = mp[0]; m[p][1] = mp[1]; m[p][2] = mp[2]; m[p][3] = mp[3];
    vv[p] = vbase[p * 8 + i];
  }

  #pragma unroll 4
  for (int ch = 0; ch < NCHUNK; ++ch) {
    const int slot = ch & 3;
    ebase[ch * 8 + i] = make_float2(er, ei);
    const float4 c0 = m[slot][0], c1 = m[slot][1];
    const float4 c2 = m[slot][2], c3 = m[slot][3];
    const float2 cv = vv[slot];
    if (ch + 4 < NCHUNK) {
      const float4* np = (const float4*)(mbase + (ch + 4) * 64 + i * 8);
      m[slot][0] = np[0]; m[slot][1] = np[1];
      m[slot][2] = np[2]; m[slot][3] = np[3];
      vv[slot] = vbase[(ch + 4) * 8 + i];
    }
    float eor[8], eoi[8];
    #pragma unroll
    for (int k = 0; k < 8; k++) {
      eor[k] = __shfl_sync(0xffffffffu, er, k, 8);
      eoi[k] = __shfl_sync(0xffffffffu, ei, k, 8);
    }
    float sr0 = cv.x, si0 = cv.y, sr1 = 0.f, si1 = 0.f;
    CMAC(sr0, si0, c0.x, c0.y, eor[0], eoi[0]);
    CMAC(sr1, si1, c0.z, c0.w, eor[1], eoi[1]);
    CMAC(sr0, si0, c1.x, c1.y, eor[2], eoi[2]);
    CMAC(sr1, si1, c1.z, c1.w, eor[3], eoi[3]);
    CMAC(sr0, si0, c2.x, c2.y, eor[4], eoi[4]);
    CMAC(sr1, si1, c2.z, c2.w, eor[5], eoi[5]);
    CMAC(sr0, si0, c3.x, c3.y, eor[6], eoi[6]);
    CMAC(sr1, si1, c3.z, c3.w, eor[7], eoi[7]);
    er = sr0 + sr1; ei = si0 + si1;
  }
}

// ---------------------------------------------------------------------------
// Kernel 3: replay each chunk from its entering state; write Y.
// Unchanged from R10 (verified): SMEM double-buffered y-broadcast.
// ---------------------------------------------------------------------------
__global__ __launch_bounds__(128) void k_replay(
    const float* __restrict__ Are, const float* __restrict__ Aim,
    const float* __restrict__ Xre, const float* __restrict__ Xim,
    float2* __restrict__ out)
{
  __shared__ __align__(16) float2 ybuf[2][16][10];

  const int tid = threadIdx.x;
  const int u = tid >> 3, j = tid & 7;
  const int bid = blockIdx.x;                // = ((b*128 + chunk)*4 + cg)
  const int cg = bid & 3;
  const int chunk = (bid >> 2) & 127;
  const int b = bid >> 9;
  const int c = cg * 16 + u;
  const int unit = (b * 64 + c) * NCHUNK + chunk;
  const int t0 = chunk * T;

  const float* arp = Are + ((size_t)(b * Lc + t0) * 64 + c) * 64 + j * 8;
  const float* aip = Aim + ((size_t)(b * Lc + t0) * 64 + c) * 64 + j * 8;
  const float* xrp = Xre + ((size_t)(b * Lc + t0) * 64 + c) * 8 + j;
  const float* xip = Xim + ((size_t)(b * Lc + t0) * 64 + c) * 8 + j;
  float2* op = out + ((size_t)(b * Lc + t0) * 64 + c) * 8 + j;

  float2 y = g_E2[unit * 8 + j];

  float4 r0 = *(const float4*)(arp), r1 = *(const float4*)(arp + 4);
  float4 i0 = *(const float4*)(aip), i1 = *(const float4*)(aip + 4);
  float xr = xrp[0], xi = xip[0];

  #pragma unroll 2
  for (int s = 0; s < T; ++s) {
    ybuf[s & 1][u][j] = y;               // publish state entering step s
    const float4 cr0 = r0, cr1 = r1, ci0 = i0, ci1 = i1;
    const float cxr = xr, cxi = xi;
    if (s < T - 1) {
      arp += 4096; aip += 4096; xrp += 512; xip += 512;
      r0 = *(const float4*)(arp); r1 = *(const float4*)(arp + 4);
      i0 = *(const float4*)(aip); i1 = *(const float4*)(aip + 4);
      xr = xrp[0]; xi = xip[0];
    }
    __syncwarp();
    const float4* yb = (const float4*)&ybuf[s & 1][u][0];
    float4 q0 = yb[0], q1 = yb[1], q2 = yb[2], q3 = yb[3];

    float sr0 = cxr, si0 = cxi, sr1 = 0.f, si1 = 0.f;
    CMAC(sr0, si0, cr0.x, ci0.x, q0.x, q0.y);
    CMAC(sr1, si1, cr0.y, ci0.y, q0.z, q0.w);
    CMAC(sr0, si0, cr0.z, ci0.z, q1.x, q1.y);
    CMAC(sr1, si1, cr0.w, ci0.w, q1.z, q1.w);
    CMAC(sr0, si0, cr1.x, ci1.x, q2.x, q2.y);
    CMAC(sr1, si1, cr1.y, ci1.y, q2.z, q2.w);
    CMAC(sr0, si0, cr1.z, ci1.z, q3.x, q3.y);
    CMAC(sr1, si1, cr1.w, ci1.w, q3.z, q3.w);
    y = make_float2(sr0 + sr1, si0 + si1);
    *op = y;
    op += 512;
  }
}

// ---------------------------------------------------------------------------
extern "C" void kernel_launch(void* const* d_in, const int* in_sizes, int n_in,
                              void* d_out, int out_size)
{
  const float* Are = (const float*)d_in[0];
  const float* Aim = (const float*)d_in[1];
  const float* Xre = (const float*)d_in[2];
  const float* Xim = (const float*)d_in[3];
  float2* out = (float2*)d_out;

  k_fold<<<4 * 128 * 8, 64>>>(Are, Aim, Xre, Xim);         // 4096 CTAs
  k_scan<<<64, 32>>>();                                    // 64 CTAs
  k_replay<<<4 * 128 * 4, 128>>>(Are, Aim, Xre, Xim, out); // 2048 CTAs
}